// round 14
// baseline (speedup 1.0000x reference)
#include <cuda_runtime.h>
#include <cuda_fp16.h>
#include <math.h>
#include <cstdint>

// ---------------- problem constants ----------------
#define Bb 2
#define Tt 2048
#define Dd 2560
#define Hh 8
#define Gg 4
#define HD 256
#define NQ (Hh*HD)     // 2048
#define NKV (Gg*HD)    // 1024
#define NQKV 4096
#define MROWS (Bb*Tt)  // 4096
#define QK_SCALE 0.0625f
#define WINDOW 1024

// ---------------- scratch ----------------------------------------------------
__device__ __align__(256) __half g_qkvh[(size_t)MROWS * NQKV];  // fp16 qkv (v in-place)
__device__ __align__(256) __half g_xh[(size_t)MROWS * Dd];
__device__ __align__(256) __half g_qh[(size_t)MROWS * NQ];
__device__ __align__(256) __half g_kh[(size_t)MROWS * NKV];
__device__ __align__(256) __half g_aoh[(size_t)MROWS * NQ];
__device__ __align__(256) __half g_wfhi[(size_t)NQKV * Dd];     // Wq|Wk|Wv [N,K]
__device__ __align__(256) __half g_wohi[(size_t)Dd * NQ];
__device__ int g_work_ctr;

// ---------------- helpers ----------------------------------------------------
__device__ __forceinline__ uint32_t smem_u32(const void* p) {
    uint32_t a;
    asm("{ .reg .u64 t; cvta.to.shared.u64 t, %1; cvt.u32.u64 %0, t; }"
        : "=r"(a) : "l"(p));
    return a;
}
__device__ __forceinline__ void cp_async16(uint32_t saddr, const void* gaddr) {
    asm volatile("cp.async.cg.shared.global [%0], [%1], 16;"
                 :: "r"(saddr), "l"(gaddr) : "memory");
}
__device__ __forceinline__ void ldmat4(uint32_t* r, uint32_t addr) {
    asm volatile("ldmatrix.sync.aligned.m8n8.x4.shared.b16 {%0,%1,%2,%3}, [%4];"
                 : "=r"(r[0]), "=r"(r[1]), "=r"(r[2]), "=r"(r[3]) : "r"(addr));
}
__device__ __forceinline__ void ldmat4t(uint32_t* r, uint32_t addr) {
    asm volatile("ldmatrix.sync.aligned.m8n8.x4.trans.shared.b16 {%0,%1,%2,%3}, [%4];"
                 : "=r"(r[0]), "=r"(r[1]), "=r"(r[2]), "=r"(r[3]) : "r"(addr));
}
__device__ __forceinline__ void mma_f16(float* c, const uint32_t* a, const uint32_t* b) {
    asm volatile(
        "mma.sync.aligned.m16n8k16.row.col.f32.f16.f16.f32 "
        "{%0,%1,%2,%3}, {%4,%5,%6,%7}, {%8,%9}, {%0,%1,%2,%3};"
        : "+f"(c[0]), "+f"(c[1]), "+f"(c[2]), "+f"(c[3])
        : "r"(a[0]), "r"(a[1]), "r"(a[2]), "r"(a[3]), "r"(b[0]), "r"(b[1]));
}

// ---------------- prep kernels ------------------------------------------------
__global__ __launch_bounds__(256) void tohalf_kernel(
    const float4* __restrict__ in, __half* __restrict__ out, int n4)
{
    int i = blockIdx.x * 256 + threadIdx.x;
    if (i >= n4) return;
    float4 v = in[i];
    __half2* op = (__half2*)(out + (size_t)i * 4);
    op[0] = __half2(__float2half_rn(v.x), __float2half_rn(v.y));
    op[1] = __half2(__float2half_rn(v.z), __float2half_rn(v.w));
}

// in [K,N] fp32 -> out [N,K] fp16
__global__ __launch_bounds__(256) void transpose_half_kernel(
    const float* __restrict__ in, __half* __restrict__ hi, int K, int N)
{
    __shared__ float t[32][33];
    int n0 = blockIdx.x * 32, k0 = blockIdx.y * 32;
    int tx = threadIdx.x & 31, ty = threadIdx.x >> 5;
#pragma unroll
    for (int i = 0; i < 32; i += 8)
        t[ty + i][tx] = in[(size_t)(k0 + ty + i) * N + n0 + tx];
    __syncthreads();
#pragma unroll
    for (int i = 0; i < 32; i += 8)
        hi[(size_t)(n0 + ty + i) * K + k0 + tx] = __float2half_rn(t[tx][ty + i]);
}

__global__ void zero_ctr_kernel() { g_work_ctr = 0; }

// ---------------- BK=64 fp16 single-pass GEMM, 3-stage pipeline ---------------
#define GPK 144
#define TILEK (128 * GPK)       // 18432
#define STAGEK (2 * TILEK)      // 36864 (A + B)
#define GSTG 3

template <typename OutT>
__global__ __launch_bounds__(256, 2) void mma_gemm64_kernel(
    const __half* __restrict__ A, const __half* __restrict__ B,
    OutT* __restrict__ C, int M, int N, int K)
{
    extern __shared__ char smem[];
    uint32_t sb = smem_u32(smem);
    int tid = threadIdx.x, lane = tid & 31, wid = tid >> 5;
    int wm = wid & 3, wn = wid >> 2;
    int row0 = blockIdx.y * 128, col0 = blockIdx.x * 128;

    const __half* gA = A + (size_t)row0 * K;
    const __half* gB = B + (size_t)col0 * K;
    const int NC = K >> 6;

    float acc[2][8][4];
#pragma unroll
    for (int mt = 0; mt < 2; mt++)
#pragma unroll
        for (int nt = 0; nt < 8; nt++)
#pragma unroll
            for (int i = 0; i < 4; i++) acc[mt][nt][i] = 0.f;

    int grp = lane >> 3, lr = lane & 7;
    uint32_t aoff = (uint32_t)(((grp & 1) * 8 + lr) * GPK + (grp >> 1) * 16);
    uint32_t boff = (uint32_t)(((grp >> 1) * 8 + lr) * GPK + (grp & 1) * 16);

    int rr = tid >> 3, cc = tid & 7;

    auto load_stage = [&](int c) {
        uint32_t st = sb + (uint32_t)(c % GSTG) * STAGEK;
        int kb = c * 64;
#pragma unroll
        for (int i = 0; i < 4; i++) {
            int r = rr + i * 32;
            uint32_t so = (uint32_t)(r * GPK + cc * 16);
            cp_async16(st + so, gA + (size_t)r * K + kb + cc * 8);
            cp_async16(st + TILEK + so, gB + (size_t)r * K + kb + cc * 8);
        }
        asm volatile("cp.async.commit_group;" ::: "memory");
    };

    load_stage(0);
    load_stage(1);

    for (int c = 0; c < NC; c++) {
        if (c + 2 < NC) {
            load_stage(c + 2);
            asm volatile("cp.async.wait_group 2;" ::: "memory");
        } else if (c + 1 < NC) {
            asm volatile("cp.async.wait_group 1;" ::: "memory");
        } else {
            asm volatile("cp.async.wait_group 0;" ::: "memory");
        }
        __syncthreads();

        uint32_t st = sb + (uint32_t)(c % GSTG) * STAGEK;
        uint32_t A0 = st, B0 = st + TILEK;

#pragma unroll
        for (int kk = 0; kk < 4; kk++) {
            uint32_t kbyte = (uint32_t)kk * 32;
            uint32_t ah[2][4], bh[8][2];
#pragma unroll
            for (int mt = 0; mt < 2; mt++) {
                uint32_t rb = (uint32_t)((wm * 32 + mt * 16) * GPK) + aoff + kbyte;
                ldmat4(ah[mt], A0 + rb);
            }
#pragma unroll
            for (int nt2 = 0; nt2 < 4; nt2++) {
                uint32_t rb = (uint32_t)((wn * 64 + nt2 * 16) * GPK) + boff + kbyte;
                uint32_t r[4];
                ldmat4(r, B0 + rb);
                bh[nt2 * 2][0] = r[0]; bh[nt2 * 2][1] = r[1];
                bh[nt2 * 2 + 1][0] = r[2]; bh[nt2 * 2 + 1][1] = r[3];
            }
#pragma unroll
            for (int mt = 0; mt < 2; mt++)
#pragma unroll
                for (int nt = 0; nt < 8; nt++)
                    mma_f16(acc[mt][nt], ah[mt], bh[nt]);
        }
        __syncthreads();
    }

#pragma unroll
    for (int mt = 0; mt < 2; mt++) {
        int rg0 = row0 + wm * 32 + mt * 16 + (lane >> 2);
#pragma unroll
        for (int nt = 0; nt < 8; nt++) {
            int cg = col0 + wn * 64 + nt * 8 + (lane & 3) * 2;
            if (sizeof(OutT) == 4) {
                *(float2*)((float*)C + (size_t)rg0 * N + cg) =
                    make_float2(acc[mt][nt][0], acc[mt][nt][1]);
                *(float2*)((float*)C + (size_t)(rg0 + 8) * N + cg) =
                    make_float2(acc[mt][nt][2], acc[mt][nt][3]);
            } else {
                __half2 h0 = __floats2half2_rn(acc[mt][nt][0], acc[mt][nt][1]);
                __half2 h1 = __floats2half2_rn(acc[mt][nt][2], acc[mt][nt][3]);
                *(__half2*)((__half*)C + (size_t)rg0 * N + cg) = h0;
                *(__half2*)((__half*)C + (size_t)(rg0 + 8) * N + cg) = h1;
            }
        }
    }
}

// ---------------- warp-per-row Gemma RMSNorm -----------------------------------
__global__ __launch_bounds__(256) void rmsnorm_qk_kernel(
    const __half* __restrict__ qkv, const float* __restrict__ qsc,
    const float* __restrict__ ksc, __half* __restrict__ qh,
    __half* __restrict__ kh)
{
    int job = blockIdx.x * 8 + (threadIdx.x >> 5);
    int lane = threadIdx.x & 31;
    int row = job / 12, hh = job % 12;

    const __half* p;
    const float* sc;
    __half* o;
    float osc;
    if (hh < 8) {
        p = qkv + (size_t)row * NQKV + hh * HD;
        o = qh + (size_t)row * NQ + hh * HD;
        sc = qsc; osc = QK_SCALE;
    } else {
        int g = hh - 8;
        p = qkv + (size_t)row * NQKV + NQ + g * HD;
        o = kh + (size_t)row * NKV + g * HD;
        sc = ksc; osc = 1.f;
    }

    uint4 raw = *(const uint4*)(p + lane * 8);
    __half2 hv[4];
    hv[0] = *(__half2*)&raw.x; hv[1] = *(__half2*)&raw.y;
    hv[2] = *(__half2*)&raw.z; hv[3] = *(__half2*)&raw.w;
    float xv[8];
#pragma unroll
    for (int i = 0; i < 4; i++) {
        float2 f = __half22float2(hv[i]);
        xv[i * 2] = f.x; xv[i * 2 + 1] = f.y;
    }
    float v = 0.f;
#pragma unroll
    for (int i = 0; i < 8; i++) v += xv[i] * xv[i];
#pragma unroll
    for (int of = 16; of > 0; of >>= 1) v += __shfl_xor_sync(0xffffffffu, v, of);

    float r = rsqrtf(v * (1.f / HD) + 1e-6f) * osc;

    float4 s0 = *(const float4*)(sc + lane * 8);
    float4 s1 = *(const float4*)(sc + lane * 8 + 4);
    float sv[8] = { s0.x, s0.y, s0.z, s0.w, s1.x, s1.y, s1.z, s1.w };

    __half2 ov[4];
#pragma unroll
    for (int i = 0; i < 4; i++)
        ov[i] = __floats2half2_rn(xv[i * 2] * r * (1.f + sv[i * 2]),
                                  xv[i * 2 + 1] * r * (1.f + sv[i * 2 + 1]));
    uint4 out;
    out.x = *(uint32_t*)&ov[0]; out.y = *(uint32_t*)&ov[1];
    out.z = *(uint32_t*)&ov[2]; out.w = *(uint32_t*)&ov[3];
    *(uint4*)(o + lane * 8) = out;
}

// ---------------- persistent FA2 attention ------------------------------------
#define NAQP 528
#define N_QB 0
#define N_KB (N_QB + 128 * NAQP)
#define N_VB (N_KB + 2 * 64 * NAQP)
#define N_TOT (N_VB + 2 * 64 * NAQP + 128)
#define NTILES (16 * Hh * Bb)   // 256

__global__ __launch_bounds__(256, 1) void attn_fa2_kernel()
{
    extern __shared__ char sm[];
    uint32_t sb = smem_u32(sm);
    __shared__ int s_w;

    int tid = threadIdx.x, lane = tid & 31, wid = tid >> 5;

    int grp = lane >> 3, lr = lane & 7;
    uint32_t aoff = (uint32_t)(((grp & 1) * 8 + lr) * NAQP + (grp >> 1) * 16);
    uint32_t boff = (uint32_t)(((grp >> 1) * 8 + lr) * NAQP + (grp & 1) * 16);
    int q4 = lane & 3;
    int row_m = wid * 16 + (lane >> 2);

    for (;;) {
        if (tid == 0) s_w = atomicAdd(&g_work_ctr, 1);
        __syncthreads();
        int w = s_w;
        if (w >= NTILES) return;

        int qt = 15 - (w >> 4);
        int hb = w & 15;
        int h = hb & 7, b = hb >> 3;
        int t0 = qt * 128;
        int kvh = h & (Gg - 1);

        const __half* qbase = g_qh + ((size_t)(b * Tt + t0)) * NQ + h * HD;
        for (int idx = tid; idx < 128 * 32; idx += 256) {
            int r = idx >> 5, c = idx & 31;
            cp_async16(sb + N_QB + (uint32_t)(r * NAQP + c * 16),
                       qbase + (size_t)r * NQ + c * 8);
        }

        int kb0 = max(0, t0 - (WINDOW - 1)) >> 6;
        int kb1 = (t0 + 127) >> 6;

        auto load_kv = [&](int kb, int buf) {
            const __half* kbase = g_kh + ((size_t)(b * Tt + kb * 64)) * NKV + kvh * HD;
            const __half* vbase = g_qkvh + ((size_t)(b * Tt + kb * 64)) * NQKV
                                  + NQ + NKV + kvh * HD;
            uint32_t kdst = sb + N_KB + (uint32_t)buf * (64 * NAQP);
            uint32_t vdst = sb + N_VB + (uint32_t)buf * (64 * NAQP);
            for (int idx = tid; idx < 64 * 32; idx += 256) {
                int r = idx >> 5, c = idx & 31;
                uint32_t so = (uint32_t)(r * NAQP + c * 16);
                cp_async16(kdst + so, kbase + (size_t)r * NKV + c * 8);
                cp_async16(vdst + so, vbase + (size_t)r * NQKV + c * 8);
            }
            asm volatile("cp.async.commit_group;" ::: "memory");
        };

        load_kv(kb0, 0);

        float o[32][4];
#pragma unroll
        for (int f = 0; f < 32; f++)
#pragma unroll
            for (int i = 0; i < 4; i++) o[f][i] = 0.f;

        float m0r = -1e30f, m1r = -1e30f;
        float l0r = 0.f, l1r = 0.f;

        int gr0 = t0 + row_m;
        int gr1 = gr0 + 8;
        int wrow_lo = t0 + wid * 16;        // warp's min q row
        int wrow_hi = wrow_lo + 15;         // warp's max q row

        for (int kb = kb0; kb <= kb1; kb++) {
            int buf = (kb - kb0) & 1;
            asm volatile("cp.async.wait_group 0;" ::: "memory");
            __syncthreads();
            if (kb < kb1) load_kv(kb + 1, buf ^ 1);

            uint32_t Kb = sb + N_KB + (uint32_t)buf * (64 * NAQP);
            uint32_t Vb = sb + N_VB + (uint32_t)buf * (64 * NAQP);
            int s0 = kb * 64;

            float sc[8][4];
#pragma unroll
            for (int j = 0; j < 8; j++)
#pragma unroll
                for (int i = 0; i < 4; i++) sc[j][i] = 0.f;
#pragma unroll 4
            for (int kd = 0; kd < 16; kd++) {
                uint32_t a[4];
                ldmat4(a, sb + N_QB + (uint32_t)(wid * 16) * NAQP + kd * 32 + aoff);
#pragma unroll
                for (int nt2 = 0; nt2 < 4; nt2++) {
                    uint32_t bf[4];
                    ldmat4(bf, Kb + (uint32_t)(nt2 * 16) * NAQP + kd * 32 + boff);
                    mma_f16(sc[nt2 * 2], a, &bf[0]);
                    mma_f16(sc[nt2 * 2 + 1], a, &bf[2]);
                }
            }

            // warp-uniform: is this k-tile fully inside the window for all 16 rows?
            bool full_tile = (s0 + 63 <= wrow_lo) && (s0 >= wrow_hi - (WINDOW - 1));

            float mx0 = -1e30f, mx1 = -1e30f;
            if (full_tile) {
#pragma unroll
                for (int j = 0; j < 8; j++) {
                    mx0 = fmaxf(mx0, fmaxf(sc[j][0], sc[j][1]));
                    mx1 = fmaxf(mx1, fmaxf(sc[j][2], sc[j][3]));
                }
            } else {
#pragma unroll
                for (int j = 0; j < 8; j++) {
                    int c0 = s0 + j * 8 + q4 * 2, c1 = c0 + 1;
                    bool a00 = (c0 <= gr0) && (c0 > gr0 - WINDOW);
                    bool a01 = (c1 <= gr0) && (c1 > gr0 - WINDOW);
                    bool a10 = (c0 <= gr1) && (c0 > gr1 - WINDOW);
                    bool a11 = (c1 <= gr1) && (c1 > gr1 - WINDOW);
                    if (a00) mx0 = fmaxf(mx0, sc[j][0]); else sc[j][0] = -1e30f;
                    if (a01) mx0 = fmaxf(mx0, sc[j][1]); else sc[j][1] = -1e30f;
                    if (a10) mx1 = fmaxf(mx1, sc[j][2]); else sc[j][2] = -1e30f;
                    if (a11) mx1 = fmaxf(mx1, sc[j][3]); else sc[j][3] = -1e30f;
                }
            }
            mx0 = fmaxf(mx0, __shfl_xor_sync(0xffffffffu, mx0, 1));
            mx0 = fmaxf(mx0, __shfl_xor_sync(0xffffffffu, mx0, 2));
            mx1 = fmaxf(mx1, __shfl_xor_sync(0xffffffffu, mx1, 1));
            mx1 = fmaxf(mx1, __shfl_xor_sync(0xffffffffu, mx1, 2));

            float mn0 = fmaxf(m0r, mx0), mn1 = fmaxf(m1r, mx1);
            float al0 = __expf(m0r - mn0), al1 = __expf(m1r - mn1);

            float s0sum = 0.f, s1sum = 0.f;
            uint32_t pfrag[8][2];
            if (full_tile) {
#pragma unroll
                for (int j = 0; j < 8; j++) {
                    float p00 = __expf(sc[j][0] - mn0);
                    float p01 = __expf(sc[j][1] - mn0);
                    float p10 = __expf(sc[j][2] - mn1);
                    float p11 = __expf(sc[j][3] - mn1);
                    s0sum += p00 + p01;
                    s1sum += p10 + p11;
                    __half2 h0 = __floats2half2_rn(p00, p01);
                    __half2 h1 = __floats2half2_rn(p10, p11);
                    pfrag[j][0] = *(uint32_t*)&h0;
                    pfrag[j][1] = *(uint32_t*)&h1;
                }
            } else {
#pragma unroll
                for (int j = 0; j < 8; j++) {
                    float p00 = (sc[j][0] > -1e29f) ? __expf(sc[j][0] - mn0) : 0.f;
                    float p01 = (sc[j][1] > -1e29f) ? __expf(sc[j][1] - mn0) : 0.f;
                    float p10 = (sc[j][2] > -1e29f) ? __expf(sc[j][2] - mn1) : 0.f;
                    float p11 = (sc[j][3] > -1e29f) ? __expf(sc[j][3] - mn1) : 0.f;
                    s0sum += p00 + p01;
                    s1sum += p10 + p11;
                    __half2 h0 = __floats2half2_rn(p00, p01);
                    __half2 h1 = __floats2half2_rn(p10, p11);
                    pfrag[j][0] = *(uint32_t*)&h0;
                    pfrag[j][1] = *(uint32_t*)&h1;
                }
            }
            s0sum += __shfl_xor_sync(0xffffffffu, s0sum, 1);
            s0sum += __shfl_xor_sync(0xffffffffu, s0sum, 2);
            s1sum += __shfl_xor_sync(0xffffffffu, s1sum, 1);
            s1sum += __shfl_xor_sync(0xffffffffu, s1sum, 2);
            l0r = l0r * al0 + s0sum;
            l1r = l1r * al1 + s1sum;
            m0r = mn0; m1r = mn1;

            // skip rescale when alpha is exactly 1 across the warp (identity)
            bool need = (al0 != 1.f) || (al1 != 1.f);
            if (__ballot_sync(0xffffffffu, need)) {
#pragma unroll
                for (int f = 0; f < 32; f++) {
                    o[f][0] *= al0; o[f][1] *= al0;
                    o[f][2] *= al1; o[f][3] *= al1;
                }
            }

#pragma unroll
            for (int kk = 0; kk < 4; kk++) {
                uint32_t pa[4];
                pa[0] = pfrag[kk * 2][0];
                pa[1] = pfrag[kk * 2][1];
                pa[2] = pfrag[kk * 2 + 1][0];
                pa[3] = pfrag[kk * 2 + 1][1];
#pragma unroll
                for (int nb = 0; nb < 16; nb++) {
                    uint32_t bv[4];
                    ldmat4t(bv, Vb + (uint32_t)(kk * 16) * NAQP
                                + (uint32_t)(nb * 32) + aoff);
                    mma_f16(o[nb * 2],     pa, &bv[0]);
                    mma_f16(o[nb * 2 + 1], pa, &bv[2]);
                }
            }
        }

        float il0 = 1.f / l0r, il1 = 1.f / l1r;
        __half* obase = g_aoh + ((size_t)(b * Tt + t0)) * NQ + h * HD;
#pragma unroll
        for (int f = 0; f < 32; f++) {
            int col = f * 8 + q4 * 2;
            __half2 h0 = __floats2half2_rn(o[f][0] * il0, o[f][1] * il0);
            __half2 h1 = __floats2half2_rn(o[f][2] * il1, o[f][3] * il1);
            *(__half2*)(obase + (size_t)row_m * NQ + col) = h0;
            *(__half2*)(obase + (size_t)(row_m + 8) * NQ + col) = h1;
        }
        __syncthreads();
    }
}

// ---------------- launch -------------------------------------------------------
extern "C" void kernel_launch(void* const* d_in, const int* in_sizes, int n_in,
                              void* d_out, int out_size)
{
    const float* x   = (const float*)d_in[0];
    const float* Wq  = (const float*)d_in[1];
    const float* Wk  = (const float*)d_in[2];
    const float* Wv  = (const float*)d_in[3];
    const float* Wo  = (const float*)d_in[4];
    const float* qsc = (const float*)d_in[5];
    const float* ksc = (const float*)d_in[6];
    float* out = (float*)d_out;

    void *pqkv, *pxh, *pqh, *pkh, *paoh, *pwfh, *pwoh;
    cudaGetSymbolAddress(&pqkv, g_qkvh);
    cudaGetSymbolAddress(&pxh, g_xh);
    cudaGetSymbolAddress(&pqh, g_qh);
    cudaGetSymbolAddress(&pkh, g_kh);
    cudaGetSymbolAddress(&paoh, g_aoh);
    cudaGetSymbolAddress(&pwfh, g_wfhi);
    cudaGetSymbolAddress(&pwoh, g_wohi);

    __half* qkvh = (__half*)pqkv;
    __half* xh  = (__half*)pxh;
    __half* qh  = (__half*)pqh;
    __half* kh  = (__half*)pkh;
    __half* aoh = (__half*)paoh;
    __half* wfh = (__half*)pwfh;
    __half* woh = (__half*)pwoh;

    size_t gemm_smem = (size_t)GSTG * STAGEK;  // 110592
    cudaFuncSetAttribute(mma_gemm64_kernel<float>,
                         cudaFuncAttributeMaxDynamicSharedMemorySize, (int)gemm_smem);
    cudaFuncSetAttribute(mma_gemm64_kernel<__half>,
                         cudaFuncAttributeMaxDynamicSharedMemorySize, (int)gemm_smem);
    cudaFuncSetAttribute(attn_fa2_kernel,
                         cudaFuncAttributeMaxDynamicSharedMemorySize, N_TOT);

    // ---- operand prep ----
    {
        int n4 = (MROWS * Dd) / 4;
        tohalf_kernel<<<(n4 + 255) / 256, 256>>>((const float4*)x, xh, n4);
        transpose_half_kernel<<<dim3(NQ / 32, Dd / 32), 256>>>(Wq, wfh, Dd, NQ);
        transpose_half_kernel<<<dim3(NKV / 32, Dd / 32), 256>>>(
            Wk, wfh + (size_t)NQ * Dd, Dd, NKV);
        transpose_half_kernel<<<dim3(NKV / 32, Dd / 32), 256>>>(
            Wv, wfh + (size_t)(NQ + NKV) * Dd, Dd, NKV);
        transpose_half_kernel<<<dim3(Dd / 32, NQ / 32), 256>>>(Wo, woh, NQ, Dd);
    }

    // ---- merged QKV projection (fp16 out, BK=64, 3-stage) ----
    mma_gemm64_kernel<__half><<<dim3(NQKV / 128, MROWS / 128), 256, gemm_smem>>>(
        xh, wfh, qkvh, MROWS, NQKV, Dd);

    // ---- qk-norm -> fp16 (warp-per-row; V stays in-place) ----
    rmsnorm_qk_kernel<<<MROWS * 12 / 8, 256>>>(qkvh, qsc, ksc, qh, kh);

    // ---- attention (persistent FA2) ----
    zero_ctr_kernel<<<1, 1>>>();
    attn_fa2_kernel<<<152, 256, N_TOT>>>();

    // ---- output projection (fp32 out, BK=64, 3-stage) ----
    mma_gemm64_kernel<float><<<dim3(Dd / 128, MROWS / 128), 256, gemm_smem>>>(
        aoh, woh, out, MROWS, Dd, NQ);
}

// round 15
// speedup vs baseline: 1.0014x; 1.0014x over previous
#include <cuda_runtime.h>
#include <cuda_fp16.h>
#include <math.h>
#include <cstdint>

// ---------------- problem constants ----------------
#define Bb 2
#define Tt 2048
#define Dd 2560
#define Hh 8
#define Gg 4
#define HD 256
#define NQ (Hh*HD)     // 2048
#define NKV (Gg*HD)    // 1024
#define NQKV 4096
#define MROWS (Bb*Tt)  // 4096
#define QK_SCALE 0.0625f
#define WINDOW 1024

// ---------------- scratch ----------------------------------------------------
__device__ __align__(256) __half g_qkvh[(size_t)MROWS * NQKV];  // fp16 qkv (v in-place)
__device__ __align__(256) __half g_xh[(size_t)MROWS * Dd];
__device__ __align__(256) __half g_qh[(size_t)MROWS * NQ];
__device__ __align__(256) __half g_kh[(size_t)MROWS * NKV];
__device__ __align__(256) __half g_aoh[(size_t)MROWS * NQ];
__device__ __align__(256) __half g_wfhi[(size_t)NQKV * Dd];     // Wq|Wk|Wv [N,K]
__device__ __align__(256) __half g_wohi[(size_t)Dd * NQ];
__device__ int g_work_ctr;

// ---------------- helpers ----------------------------------------------------
__device__ __forceinline__ uint32_t smem_u32(const void* p) {
    uint32_t a;
    asm("{ .reg .u64 t; cvta.to.shared.u64 t, %1; cvt.u32.u64 %0, t; }"
        : "=r"(a) : "l"(p));
    return a;
}
__device__ __forceinline__ void cp_async16(uint32_t saddr, const void* gaddr) {
    asm volatile("cp.async.cg.shared.global [%0], [%1], 16;"
                 :: "r"(saddr), "l"(gaddr) : "memory");
}
__device__ __forceinline__ void ldmat4(uint32_t* r, uint32_t addr) {
    asm volatile("ldmatrix.sync.aligned.m8n8.x4.shared.b16 {%0,%1,%2,%3}, [%4];"
                 : "=r"(r[0]), "=r"(r[1]), "=r"(r[2]), "=r"(r[3]) : "r"(addr));
}
__device__ __forceinline__ void ldmat4t(uint32_t* r, uint32_t addr) {
    asm volatile("ldmatrix.sync.aligned.m8n8.x4.trans.shared.b16 {%0,%1,%2,%3}, [%4];"
                 : "=r"(r[0]), "=r"(r[1]), "=r"(r[2]), "=r"(r[3]) : "r"(addr));
}
__device__ __forceinline__ void mma_f16(float* c, const uint32_t* a, const uint32_t* b) {
    asm volatile(
        "mma.sync.aligned.m16n8k16.row.col.f32.f16.f16.f32 "
        "{%0,%1,%2,%3}, {%4,%5,%6,%7}, {%8,%9}, {%0,%1,%2,%3};"
        : "+f"(c[0]), "+f"(c[1]), "+f"(c[2]), "+f"(c[3])
        : "r"(a[0]), "r"(a[1]), "r"(a[2]), "r"(a[3]), "r"(b[0]), "r"(b[1]));
}

// ---------------- prep kernels ------------------------------------------------
__global__ __launch_bounds__(256) void tohalf_kernel(
    const float4* __restrict__ in, __half* __restrict__ out, int n4)
{
    int i = blockIdx.x * 256 + threadIdx.x;
    if (i >= n4) return;
    float4 v = in[i];
    __half2* op = (__half2*)(out + (size_t)i * 4);
    op[0] = __half2(__float2half_rn(v.x), __float2half_rn(v.y));
    op[1] = __half2(__float2half_rn(v.z), __float2half_rn(v.w));
}

// in [K,N] fp32 -> out [N,K] fp16
__global__ __launch_bounds__(256) void transpose_half_kernel(
    const float* __restrict__ in, __half* __restrict__ hi, int K, int N)
{
    __shared__ float t[32][33];
    int n0 = blockIdx.x * 32, k0 = blockIdx.y * 32;
    int tx = threadIdx.x & 31, ty = threadIdx.x >> 5;
#pragma unroll
    for (int i = 0; i < 32; i += 8)
        t[ty + i][tx] = in[(size_t)(k0 + ty + i) * N + n0 + tx];
    __syncthreads();
#pragma unroll
    for (int i = 0; i < 32; i += 8)
        hi[(size_t)(n0 + ty + i) * K + k0 + tx] = __float2half_rn(t[tx][ty + i]);
}

__global__ void zero_ctr_kernel() { g_work_ctr = 0; }

// ---------------- BK=64 fp16 single-pass GEMM (2-stage, R13) -------------------
#define GPK 144
#define TILEK (128 * GPK)       // 18432
#define STAGEK (2 * TILEK)      // 36864 (A + B)

template <typename OutT>
__global__ __launch_bounds__(256, 2) void mma_gemm64_kernel(
    const __half* __restrict__ A, const __half* __restrict__ B,
    OutT* __restrict__ C, int M, int N, int K)
{
    extern __shared__ char smem[];
    uint32_t sb = smem_u32(smem);
    int tid = threadIdx.x, lane = tid & 31, wid = tid >> 5;
    int wm = wid & 3, wn = wid >> 2;
    int row0 = blockIdx.y * 128, col0 = blockIdx.x * 128;

    const __half* gA = A + (size_t)row0 * K;
    const __half* gB = B + (size_t)col0 * K;
    const int NC = K >> 6;

    float acc[2][8][4];
#pragma unroll
    for (int mt = 0; mt < 2; mt++)
#pragma unroll
        for (int nt = 0; nt < 8; nt++)
#pragma unroll
            for (int i = 0; i < 4; i++) acc[mt][nt][i] = 0.f;

    int grp = lane >> 3, lr = lane & 7;
    uint32_t aoff = (uint32_t)(((grp & 1) * 8 + lr) * GPK + (grp >> 1) * 16);
    uint32_t boff = (uint32_t)(((grp >> 1) * 8 + lr) * GPK + (grp & 1) * 16);

    int rr = tid >> 3, cc = tid & 7;

    auto load_stage = [&](int c) {
        uint32_t st = sb + (uint32_t)(c & 1) * STAGEK;
        int kb = c * 64;
#pragma unroll
        for (int i = 0; i < 4; i++) {
            int r = rr + i * 32;
            uint32_t so = (uint32_t)(r * GPK + cc * 16);
            cp_async16(st + so, gA + (size_t)r * K + kb + cc * 8);
            cp_async16(st + TILEK + so, gB + (size_t)r * K + kb + cc * 8);
        }
        asm volatile("cp.async.commit_group;" ::: "memory");
    };

    load_stage(0);

    for (int c = 0; c < NC; c++) {
        if (c + 1 < NC) {
            load_stage(c + 1);
            asm volatile("cp.async.wait_group 1;" ::: "memory");
        } else {
            asm volatile("cp.async.wait_group 0;" ::: "memory");
        }
        __syncthreads();

        uint32_t st = sb + (uint32_t)(c & 1) * STAGEK;
        uint32_t A0 = st, B0 = st + TILEK;

#pragma unroll
        for (int kk = 0; kk < 4; kk++) {
            uint32_t kbyte = (uint32_t)kk * 32;
            uint32_t ah[2][4], bh[8][2];
#pragma unroll
            for (int mt = 0; mt < 2; mt++) {
                uint32_t rb = (uint32_t)((wm * 32 + mt * 16) * GPK) + aoff + kbyte;
                ldmat4(ah[mt], A0 + rb);
            }
#pragma unroll
            for (int nt2 = 0; nt2 < 4; nt2++) {
                uint32_t rb = (uint32_t)((wn * 64 + nt2 * 16) * GPK) + boff + kbyte;
                uint32_t r[4];
                ldmat4(r, B0 + rb);
                bh[nt2 * 2][0] = r[0]; bh[nt2 * 2][1] = r[1];
                bh[nt2 * 2 + 1][0] = r[2]; bh[nt2 * 2 + 1][1] = r[3];
            }
#pragma unroll
            for (int mt = 0; mt < 2; mt++)
#pragma unroll
                for (int nt = 0; nt < 8; nt++)
                    mma_f16(acc[mt][nt], ah[mt], bh[nt]);
        }
        __syncthreads();
    }

#pragma unroll
    for (int mt = 0; mt < 2; mt++) {
        int rg0 = row0 + wm * 32 + mt * 16 + (lane >> 2);
#pragma unroll
        for (int nt = 0; nt < 8; nt++) {
            int cg = col0 + wn * 64 + nt * 8 + (lane & 3) * 2;
            if (sizeof(OutT) == 4) {
                *(float2*)((float*)C + (size_t)rg0 * N + cg) =
                    make_float2(acc[mt][nt][0], acc[mt][nt][1]);
                *(float2*)((float*)C + (size_t)(rg0 + 8) * N + cg) =
                    make_float2(acc[mt][nt][2], acc[mt][nt][3]);
            } else {
                __half2 h0 = __floats2half2_rn(acc[mt][nt][0], acc[mt][nt][1]);
                __half2 h1 = __floats2half2_rn(acc[mt][nt][2], acc[mt][nt][3]);
                *(__half2*)((__half*)C + (size_t)rg0 * N + cg) = h0;
                *(__half2*)((__half*)C + (size_t)(rg0 + 8) * N + cg) = h1;
            }
        }
    }
}

// ---------------- warp-per-row Gemma RMSNorm -----------------------------------
__global__ __launch_bounds__(256) void rmsnorm_qk_kernel(
    const __half* __restrict__ qkv, const float* __restrict__ qsc,
    const float* __restrict__ ksc, __half* __restrict__ qh,
    __half* __restrict__ kh)
{
    int job = blockIdx.x * 8 + (threadIdx.x >> 5);
    int lane = threadIdx.x & 31;
    int row = job / 12, hh = job % 12;

    const __half* p;
    const float* sc;
    __half* o;
    float osc;
    if (hh < 8) {
        p = qkv + (size_t)row * NQKV + hh * HD;
        o = qh + (size_t)row * NQ + hh * HD;
        sc = qsc; osc = QK_SCALE;
    } else {
        int g = hh - 8;
        p = qkv + (size_t)row * NQKV + NQ + g * HD;
        o = kh + (size_t)row * NKV + g * HD;
        sc = ksc; osc = 1.f;
    }

    uint4 raw = *(const uint4*)(p + lane * 8);
    __half2 hv[4];
    hv[0] = *(__half2*)&raw.x; hv[1] = *(__half2*)&raw.y;
    hv[2] = *(__half2*)&raw.z; hv[3] = *(__half2*)&raw.w;
    float xv[8];
#pragma unroll
    for (int i = 0; i < 4; i++) {
        float2 f = __half22float2(hv[i]);
        xv[i * 2] = f.x; xv[i * 2 + 1] = f.y;
    }
    float v = 0.f;
#pragma unroll
    for (int i = 0; i < 8; i++) v += xv[i] * xv[i];
#pragma unroll
    for (int of = 16; of > 0; of >>= 1) v += __shfl_xor_sync(0xffffffffu, v, of);

    float r = rsqrtf(v * (1.f / HD) + 1e-6f) * osc;

    float4 s0 = *(const float4*)(sc + lane * 8);
    float4 s1 = *(const float4*)(sc + lane * 8 + 4);
    float sv[8] = { s0.x, s0.y, s0.z, s0.w, s1.x, s1.y, s1.z, s1.w };

    __half2 ov[4];
#pragma unroll
    for (int i = 0; i < 4; i++)
        ov[i] = __floats2half2_rn(xv[i * 2] * r * (1.f + sv[i * 2]),
                                  xv[i * 2 + 1] * r * (1.f + sv[i * 2 + 1]));
    uint4 out;
    out.x = *(uint32_t*)&ov[0]; out.y = *(uint32_t*)&ov[1];
    out.z = *(uint32_t*)&ov[2]; out.w = *(uint32_t*)&ov[3];
    *(uint4*)(o + lane * 8) = out;
}

// ---------------- persistent FA2 attention (exp/PV interleaved) ----------------
#define NAQP 528
#define N_QB 0
#define N_KB (N_QB + 128 * NAQP)
#define N_VB (N_KB + 2 * 64 * NAQP)
#define N_TOT (N_VB + 2 * 64 * NAQP + 128)
#define NTILES (16 * Hh * Bb)   // 256

__global__ __launch_bounds__(256, 1) void attn_fa2_kernel()
{
    extern __shared__ char sm[];
    uint32_t sb = smem_u32(sm);
    __shared__ int s_w;

    int tid = threadIdx.x, lane = tid & 31, wid = tid >> 5;

    int grp = lane >> 3, lr = lane & 7;
    uint32_t aoff = (uint32_t)(((grp & 1) * 8 + lr) * NAQP + (grp >> 1) * 16);
    uint32_t boff = (uint32_t)(((grp >> 1) * 8 + lr) * NAQP + (grp & 1) * 16);
    int q4 = lane & 3;
    int row_m = wid * 16 + (lane >> 2);

    for (;;) {
        if (tid == 0) s_w = atomicAdd(&g_work_ctr, 1);
        __syncthreads();
        int w = s_w;
        if (w >= NTILES) return;

        int qt = 15 - (w >> 4);
        int hb = w & 15;
        int h = hb & 7, b = hb >> 3;
        int t0 = qt * 128;
        int kvh = h & (Gg - 1);

        const __half* qbase = g_qh + ((size_t)(b * Tt + t0)) * NQ + h * HD;
        for (int idx = tid; idx < 128 * 32; idx += 256) {
            int r = idx >> 5, c = idx & 31;
            cp_async16(sb + N_QB + (uint32_t)(r * NAQP + c * 16),
                       qbase + (size_t)r * NQ + c * 8);
        }

        int kb0 = max(0, t0 - (WINDOW - 1)) >> 6;
        int kb1 = (t0 + 127) >> 6;

        auto load_kv = [&](int kb, int buf) {
            const __half* kbase = g_kh + ((size_t)(b * Tt + kb * 64)) * NKV + kvh * HD;
            const __half* vbase = g_qkvh + ((size_t)(b * Tt + kb * 64)) * NQKV
                                  + NQ + NKV + kvh * HD;
            uint32_t kdst = sb + N_KB + (uint32_t)buf * (64 * NAQP);
            uint32_t vdst = sb + N_VB + (uint32_t)buf * (64 * NAQP);
            for (int idx = tid; idx < 64 * 32; idx += 256) {
                int r = idx >> 5, c = idx & 31;
                uint32_t so = (uint32_t)(r * NAQP + c * 16);
                cp_async16(kdst + so, kbase + (size_t)r * NKV + c * 8);
                cp_async16(vdst + so, vbase + (size_t)r * NQKV + c * 8);
            }
            asm volatile("cp.async.commit_group;" ::: "memory");
        };

        load_kv(kb0, 0);

        float o[32][4];
#pragma unroll
        for (int f = 0; f < 32; f++)
#pragma unroll
            for (int i = 0; i < 4; i++) o[f][i] = 0.f;

        float m0r = -1e30f, m1r = -1e30f;
        float l0r = 0.f, l1r = 0.f;

        int gr0 = t0 + row_m;
        int gr1 = gr0 + 8;

        for (int kb = kb0; kb <= kb1; kb++) {
            int buf = (kb - kb0) & 1;
            asm volatile("cp.async.wait_group 0;" ::: "memory");
            __syncthreads();
            if (kb < kb1) load_kv(kb + 1, buf ^ 1);

            uint32_t Kb = sb + N_KB + (uint32_t)buf * (64 * NAQP);
            uint32_t Vb = sb + N_VB + (uint32_t)buf * (64 * NAQP);
            int s0 = kb * 64;

            // ---- QK ----
            float sc[8][4];
#pragma unroll
            for (int j = 0; j < 8; j++)
#pragma unroll
                for (int i = 0; i < 4; i++) sc[j][i] = 0.f;
#pragma unroll 4
            for (int kd = 0; kd < 16; kd++) {
                uint32_t a[4];
                ldmat4(a, sb + N_QB + (uint32_t)(wid * 16) * NAQP + kd * 32 + aoff);
#pragma unroll
                for (int nt2 = 0; nt2 < 4; nt2++) {
                    uint32_t bf[4];
                    ldmat4(bf, Kb + (uint32_t)(nt2 * 16) * NAQP + kd * 32 + boff);
                    mma_f16(sc[nt2 * 2], a, &bf[0]);
                    mma_f16(sc[nt2 * 2 + 1], a, &bf[2]);
                }
            }

            // ---- mask + row max ----
            float mx0 = -1e30f, mx1 = -1e30f;
#pragma unroll
            for (int j = 0; j < 8; j++) {
                int c0 = s0 + j * 8 + q4 * 2, c1 = c0 + 1;
                bool a00 = (c0 <= gr0) && (c0 > gr0 - WINDOW);
                bool a01 = (c1 <= gr0) && (c1 > gr0 - WINDOW);
                bool a10 = (c0 <= gr1) && (c0 > gr1 - WINDOW);
                bool a11 = (c1 <= gr1) && (c1 > gr1 - WINDOW);
                if (a00) mx0 = fmaxf(mx0, sc[j][0]); else sc[j][0] = -1e30f;
                if (a01) mx0 = fmaxf(mx0, sc[j][1]); else sc[j][1] = -1e30f;
                if (a10) mx1 = fmaxf(mx1, sc[j][2]); else sc[j][2] = -1e30f;
                if (a11) mx1 = fmaxf(mx1, sc[j][3]); else sc[j][3] = -1e30f;
            }
            mx0 = fmaxf(mx0, __shfl_xor_sync(0xffffffffu, mx0, 1));
            mx0 = fmaxf(mx0, __shfl_xor_sync(0xffffffffu, mx0, 2));
            mx1 = fmaxf(mx1, __shfl_xor_sync(0xffffffffu, mx1, 1));
            mx1 = fmaxf(mx1, __shfl_xor_sync(0xffffffffu, mx1, 2));

            float mn0 = fmaxf(m0r, mx0), mn1 = fmaxf(m1r, mx1);
            float al0 = __expf(m0r - mn0), al1 = __expf(m1r - mn1);

            // ---- rescale O (overlaps first exp batch via pipe separation) ----
#pragma unroll
            for (int f = 0; f < 32; f++) {
                o[f][0] *= al0; o[f][1] *= al0;
                o[f][2] *= al1; o[f][3] *= al1;
            }

            // ---- interleaved exp + PV: per k-slice, exp 2 frags then 32 MMAs ----
            float s0sum = 0.f, s1sum = 0.f;
#pragma unroll
            for (int kk = 0; kk < 4; kk++) {
                uint32_t pa[4];
#pragma unroll
                for (int jj = 0; jj < 2; jj++) {
                    int j = kk * 2 + jj;
                    float p00 = (sc[j][0] > -1e29f) ? __expf(sc[j][0] - mn0) : 0.f;
                    float p01 = (sc[j][1] > -1e29f) ? __expf(sc[j][1] - mn0) : 0.f;
                    float p10 = (sc[j][2] > -1e29f) ? __expf(sc[j][2] - mn1) : 0.f;
                    float p11 = (sc[j][3] > -1e29f) ? __expf(sc[j][3] - mn1) : 0.f;
                    s0sum += p00 + p01;
                    s1sum += p10 + p11;
                    __half2 h0 = __floats2half2_rn(p00, p01);
                    __half2 h1 = __floats2half2_rn(p10, p11);
                    pa[jj * 2]     = *(uint32_t*)&h0;
                    pa[jj * 2 + 1] = *(uint32_t*)&h1;
                }
#pragma unroll
                for (int nb = 0; nb < 16; nb++) {
                    uint32_t bv[4];
                    ldmat4t(bv, Vb + (uint32_t)(kk * 16) * NAQP
                                + (uint32_t)(nb * 32) + aoff);
                    mma_f16(o[nb * 2],     pa, &bv[0]);
                    mma_f16(o[nb * 2 + 1], pa, &bv[2]);
                }
            }
            s0sum += __shfl_xor_sync(0xffffffffu, s0sum, 1);
            s0sum += __shfl_xor_sync(0xffffffffu, s0sum, 2);
            s1sum += __shfl_xor_sync(0xffffffffu, s1sum, 1);
            s1sum += __shfl_xor_sync(0xffffffffu, s1sum, 2);
            l0r = l0r * al0 + s0sum;
            l1r = l1r * al1 + s1sum;
            m0r = mn0; m1r = mn1;
        }

        float il0 = 1.f / l0r, il1 = 1.f / l1r;
        __half* obase = g_aoh + ((size_t)(b * Tt + t0)) * NQ + h * HD;
#pragma unroll
        for (int f = 0; f < 32; f++) {
            int col = f * 8 + q4 * 2;
            __half2 h0 = __floats2half2_rn(o[f][0] * il0, o[f][1] * il0);
            __half2 h1 = __floats2half2_rn(o[f][2] * il1, o[f][3] * il1);
            *(__half2*)(obase + (size_t)row_m * NQ + col) = h0;
            *(__half2*)(obase + (size_t)(row_m + 8) * NQ + col) = h1;
        }
        __syncthreads();
    }
}

// ---------------- launch -------------------------------------------------------
extern "C" void kernel_launch(void* const* d_in, const int* in_sizes, int n_in,
                              void* d_out, int out_size)
{
    const float* x   = (const float*)d_in[0];
    const float* Wq  = (const float*)d_in[1];
    const float* Wk  = (const float*)d_in[2];
    const float* Wv  = (const float*)d_in[3];
    const float* Wo  = (const float*)d_in[4];
    const float* qsc = (const float*)d_in[5];
    const float* ksc = (const float*)d_in[6];
    float* out = (float*)d_out;

    void *pqkv, *pxh, *pqh, *pkh, *paoh, *pwfh, *pwoh;
    cudaGetSymbolAddress(&pqkv, g_qkvh);
    cudaGetSymbolAddress(&pxh, g_xh);
    cudaGetSymbolAddress(&pqh, g_qh);
    cudaGetSymbolAddress(&pkh, g_kh);
    cudaGetSymbolAddress(&paoh, g_aoh);
    cudaGetSymbolAddress(&pwfh, g_wfhi);
    cudaGetSymbolAddress(&pwoh, g_wohi);

    __half* qkvh = (__half*)pqkv;
    __half* xh  = (__half*)pxh;
    __half* qh  = (__half*)pqh;
    __half* kh  = (__half*)pkh;
    __half* aoh = (__half*)paoh;
    __half* wfh = (__half*)pwfh;
    __half* woh = (__half*)pwoh;

    size_t gemm_smem = 2 * STAGEK;  // 73728
    cudaFuncSetAttribute(mma_gemm64_kernel<float>,
                         cudaFuncAttributeMaxDynamicSharedMemorySize, (int)gemm_smem);
    cudaFuncSetAttribute(mma_gemm64_kernel<__half>,
                         cudaFuncAttributeMaxDynamicSharedMemorySize, (int)gemm_smem);
    cudaFuncSetAttribute(attn_fa2_kernel,
                         cudaFuncAttributeMaxDynamicSharedMemorySize, N_TOT);

    // ---- operand prep ----
    {
        int n4 = (MROWS * Dd) / 4;
        tohalf_kernel<<<(n4 + 255) / 256, 256>>>((const float4*)x, xh, n4);
        transpose_half_kernel<<<dim3(NQ / 32, Dd / 32), 256>>>(Wq, wfh, Dd, NQ);
        transpose_half_kernel<<<dim3(NKV / 32, Dd / 32), 256>>>(
            Wk, wfh + (size_t)NQ * Dd, Dd, NKV);
        transpose_half_kernel<<<dim3(NKV / 32, Dd / 32), 256>>>(
            Wv, wfh + (size_t)(NQ + NKV) * Dd, Dd, NKV);
        transpose_half_kernel<<<dim3(Dd / 32, NQ / 32), 256>>>(Wo, woh, NQ, Dd);
    }

    // ---- merged QKV projection (fp16 out, BK=64) ----
    mma_gemm64_kernel<__half><<<dim3(NQKV / 128, MROWS / 128), 256, gemm_smem>>>(
        xh, wfh, qkvh, MROWS, NQKV, Dd);

    // ---- qk-norm -> fp16 (warp-per-row; V stays in-place) ----
    rmsnorm_qk_kernel<<<MROWS * 12 / 8, 256>>>(qkvh, qsc, ksc, qh, kh);

    // ---- attention (persistent FA2, exp/PV interleaved) ----
    zero_ctr_kernel<<<1, 1>>>();
    attn_fa2_kernel<<<152, 256, N_TOT>>>();

    // ---- output projection (fp32 out, BK=64) ----
    mma_gemm64_kernel<float><<<dim3(Dd / 128, MROWS / 128), 256, gemm_smem>>>(
        aoh, woh, out, MROWS, Dd, NQ);
}